// round 4
// baseline (speedup 1.0000x reference)
#include <cuda_runtime.h>
#include <cuda_bf16.h>

// ---------------- problem constants (fixed shapes) ----------------
#define T_TOK   2048      // B*S
#define HDIM    1024      // H
#define NEXP    64        // E
#define IDIM    512       // expert intermediate I
#define ISH     2048      // shared intermediate Is
#define TOPK    8
#define CAP     512
#define NASSIGN (T_TOK*TOPK)

// ---------------- scratch (device globals; no allocation) ----------------
__device__ float g_shared_act[T_TOK * ISH];           // [2048,2048] 16.8MB
__device__ float g_act[NEXP * CAP * IDIM];            // [64,512,512] 67MB
__device__ float g_outbuf[(long long)NEXP * CAP * HDIM]; // [64,512,1024] 134MB
__device__ float g_sg[T_TOK];
__device__ int   g_counts[NEXP];
__device__ int   g_expert_tok[NEXP * CAP];
__device__ int   g_assign_e[NASSIGN];
__device__ int   g_assign_slot[NASSIGN];
__device__ float g_assign_w[NASSIGN];

// ---------------- misc ----------------
__global__ void zero_counts_kernel() {
    if (threadIdx.x < NEXP) g_counts[threadIdx.x] = 0;
}

// ---------------- router: logits -> softmax -> top8 -> dispatch; also shared sigmoid gate ----------------
__global__ void router_kernel(const float* __restrict__ X,
                              const float* __restrict__ Wg,   // [H, E]
                              const float* __restrict__ Wsg)  // [H, 1]
{
    __shared__ float xs[HDIM];
    __shared__ float red[256];
    __shared__ float logits[NEXP];

    const int t   = blockIdx.x;
    const int tid = threadIdx.x;
    const float* x = X + (long long)t * HDIM;

    for (int i = tid; i < HDIM; i += 256) xs[i] = x[i];
    __syncthreads();

    // logits: 4 threads per expert
    {
        const int e = tid >> 2, r = tid & 3;
        float s = 0.f;
        for (int k = r; k < HDIM; k += 4) s += xs[k] * Wg[k * NEXP + e];
        s += __shfl_down_sync(0xffffffffu, s, 2);
        s += __shfl_down_sync(0xffffffffu, s, 1);
        if (r == 0) logits[e] = s;
    }

    // shared sigmoid gate partial
    {
        float p = 0.f;
        for (int k = tid; k < HDIM; k += 256) p += xs[k] * Wsg[k];
        red[tid] = p;
    }
    __syncthreads();

    if (tid == 0) {
        float tot = 0.f;
        for (int i = 0; i < 256; i++) tot += red[i];
        g_sg[t] = 1.f / (1.f + __expf(-tot));

        // fp32 softmax
        float mx = logits[0];
        for (int i = 1; i < NEXP; i++) mx = fmaxf(mx, logits[i]);
        float pr[NEXP];
        float Z = 0.f;
        for (int i = 0; i < NEXP; i++) { pr[i] = __expf(logits[i] - mx); Z += pr[i]; }

        // top-8 (first-index tie behavior matches jax top_k)
        int   eidx[TOPK];
        float wv[TOPK];
        float wsum = 0.f;
        for (int k = 0; k < TOPK; k++) {
            int best = 0; float bv = -1.f;
            for (int i = 0; i < NEXP; i++) if (pr[i] > bv) { bv = pr[i]; best = i; }
            eidx[k] = best; wv[k] = bv / Z; pr[best] = -1.f;
            wsum += wv[k];
        }
        for (int k = 0; k < TOPK; k++) {
            const float w = wv[k] / wsum;
            const int   e = eidx[k];
            const int   a = t * TOPK + k;
            const int slot = atomicAdd(&g_counts[e], 1);
            g_assign_e[a] = e;
            g_assign_w[a] = w;
            if (slot < CAP) {
                g_assign_slot[a] = slot;
                g_expert_tok[e * CAP + slot] = t;
            } else {
                g_assign_slot[a] = CAP;   // overflow -> dropped in combine
            }
        }
    }
}

// ---------------- fused GEMM + SwiGLU ----------------
// C[g][m][n] = silu(sum_k A[row(m)][k]*Bg[k][n]) * (sum_k A[row(m)][k]*Bu[k][n])
#define BM 64
#define BN 64
#define BK 16

__global__ void gemm_swiglu_kernel(
    const float* __restrict__ X,       // [*, K] rows gathered
    const float* __restrict__ Bmat,    // gate_up base
    const int*   __restrict__ rowlist, // null => identity rows
    const int*   __restrict__ counts,  // null => use Mfixed
    float*       __restrict__ Cact,
    int K, int N, int ldb, int upoff,
    long long strideB, long long strideC,
    int Mfixed, int Mcap)
{
    const int g  = blockIdx.z;
    const int Mg = counts ? min(counts[g], Mcap) : Mfixed;
    const int m0 = blockIdx.y * BM;
    if (m0 >= Mg) return;
    const int n0 = blockIdx.x * BN;

    const float* Bg = Bmat + (long long)g * strideB;
    const float* Bu = Bg + upoff;
    float* C = Cact + (long long)g * strideC;
    const int* rl = rowlist ? (rowlist + g * Mcap) : nullptr;

    __shared__ float As[BK][BM];
    __shared__ float Bgs[BK][BN];
    __shared__ float Bus[BK][BN];

    const int tid  = threadIdx.x;
    const int aRow = tid >> 2;
    const int aK   = (tid & 3) * 4;
    const int bRow = tid >> 4;
    const int bCol = (tid & 15) * 4;
    const int ty   = tid >> 4;
    const int tx   = tid & 15;

    const float* Arow = nullptr;
    {
        const int mloc = m0 + aRow;
        if (mloc < Mg) {
            const int grow = rl ? rl[mloc] : mloc;
            Arow = X + (long long)grow * K;
        }
    }

    float accG[4][4]; float accU[4][4];
    #pragma unroll
    for (int i = 0; i < 4; i++)
        #pragma unroll
        for (int j = 0; j < 4; j++) { accG[i][j] = 0.f; accU[i][j] = 0.f; }

    for (int k0 = 0; k0 < K; k0 += BK) {
        float4 av = make_float4(0.f, 0.f, 0.f, 0.f);
        if (Arow) av = *(const float4*)(Arow + k0 + aK);
        As[aK + 0][aRow] = av.x;
        As[aK + 1][aRow] = av.y;
        As[aK + 2][aRow] = av.z;
        As[aK + 3][aRow] = av.w;
        *(float4*)&Bgs[bRow][bCol] = *(const float4*)(Bg + (long long)(k0 + bRow) * ldb + n0 + bCol);
        *(float4*)&Bus[bRow][bCol] = *(const float4*)(Bu + (long long)(k0 + bRow) * ldb + n0 + bCol);
        __syncthreads();

        #pragma unroll
        for (int kk = 0; kk < BK; kk++) {
            const float4 a   = *(const float4*)&As[kk][ty * 4];
            const float4 bgv = *(const float4*)&Bgs[kk][tx * 4];
            const float4 buv = *(const float4*)&Bus[kk][tx * 4];
            const float aa[4] = {a.x, a.y, a.z, a.w};
            const float bg4[4] = {bgv.x, bgv.y, bgv.z, bgv.w};
            const float bu4[4] = {buv.x, buv.y, buv.z, buv.w};
            #pragma unroll
            for (int i = 0; i < 4; i++)
                #pragma unroll
                for (int j = 0; j < 4; j++) {
                    accG[i][j] += aa[i] * bg4[j];
                    accU[i][j] += aa[i] * bu4[j];
                }
        }
        __syncthreads();
    }

    #pragma unroll
    for (int i = 0; i < 4; i++) {
        const int m = m0 + ty * 4 + i;
        if (m >= Mg) continue;
        #pragma unroll
        for (int j = 0; j < 4; j++) {
            const int n = n0 + tx * 4 + j;
            const float gv = accG[i][j];
            const float uv = accU[i][j];
            C[(long long)m * N + n] = (gv / (1.f + __expf(-gv))) * uv;
        }
    }
}

// ---------------- plain down GEMM (optional per-row scale) ----------------
__global__ void gemm_down_kernel(
    const float* __restrict__ Amat,
    const float* __restrict__ Bmat,
    float*       __restrict__ Cmat,
    const int*   __restrict__ counts,
    const float* __restrict__ rowscale,
    int K, int N,
    long long strideA, long long strideB, long long strideC,
    int Mfixed, int Mcap)
{
    const int g  = blockIdx.z;
    const int Mg = counts ? min(counts[g], Mcap) : Mfixed;
    const int m0 = blockIdx.y * BM;
    if (m0 >= Mg) return;
    const int n0 = blockIdx.x * BN;

    const float* A = Amat + (long long)g * strideA;
    const float* B = Bmat + (long long)g * strideB;
    float* C = Cmat + (long long)g * strideC;

    __shared__ float As[BK][BM];
    __shared__ float Bs[BK][BN];

    const int tid  = threadIdx.x;
    const int aRow = tid >> 2;
    const int aK   = (tid & 3) * 4;
    const int bRow = tid >> 4;
    const int bCol = (tid & 15) * 4;
    const int ty   = tid >> 4;
    const int tx   = tid & 15;

    const bool arow_ok = (m0 + aRow) < Mg;
    const float* Arow = A + (long long)(m0 + aRow) * K;

    float acc[4][4];
    #pragma unroll
    for (int i = 0; i < 4; i++)
        #pragma unroll
        for (int j = 0; j < 4; j++) acc[i][j] = 0.f;

    for (int k0 = 0; k0 < K; k0 += BK) {
        float4 av = make_float4(0.f, 0.f, 0.f, 0.f);
        if (arow_ok) av = *(const float4*)(Arow + k0 + aK);
        As[aK + 0][aRow] = av.x;
        As[aK + 1][aRow] = av.y;
        As[aK + 2][aRow] = av.z;
        As[aK + 3][aRow] = av.w;
        *(float4*)&Bs[bRow][bCol] = *(const float4*)(B + (long long)(k0 + bRow) * N + n0 + bCol);
        __syncthreads();

        #pragma unroll
        for (int kk = 0; kk < BK; kk++) {
            const float4 a  = *(const float4*)&As[kk][ty * 4];
            const float4 bv = *(const float4*)&Bs[kk][tx * 4];
            const float aa[4] = {a.x, a.y, a.z, a.w};
            const float bb[4] = {bv.x, bv.y, bv.z, bv.w};
            #pragma unroll
            for (int i = 0; i < 4; i++)
                #pragma unroll
                for (int j = 0; j < 4; j++) acc[i][j] += aa[i] * bb[j];
        }
        __syncthreads();
    }

    #pragma unroll
    for (int i = 0; i < 4; i++) {
        const int m = m0 + ty * 4 + i;
        if (m >= Mg) continue;
        const float sc = rowscale ? rowscale[m] : 1.f;
        #pragma unroll
        for (int j = 0; j < 4; j++) {
            const int n = n0 + tx * 4 + j;
            C[(long long)m * N + n] = sc * acc[i][j];
        }
    }
}

// ---------------- combine: out[t] = shared[t] + sum_k w * outbuf[e_k, slot_k] ----------------
__global__ void combine_kernel(float* __restrict__ out)
{
    const int t = blockIdx.x;
    const int h = threadIdx.x * 4;
    float4 acc = *(float4*)(out + (long long)t * HDIM + h);
    #pragma unroll
    for (int k = 0; k < TOPK; k++) {
        const int a = t * TOPK + k;
        const int e = g_assign_e[a];
        const int s = g_assign_slot[a];
        const float w = g_assign_w[a];
        if (s < CAP) {
            const float4 v = *(const float4*)(g_outbuf + ((long long)(e * CAP + s)) * HDIM + h);
            acc.x += w * v.x; acc.y += w * v.y; acc.z += w * v.z; acc.w += w * v.w;
        }
    }
    *(float4*)(out + (long long)t * HDIM + h) = acc;
}

// ---------------- host launch ----------------
extern "C" void kernel_launch(void* const* d_in, const int* in_sizes, int n_in,
                              void* d_out, int out_size)
{
    const float* x    = (const float*)d_in[0]; // [2,1024,1024] -> [2048,1024]
    const float* wg   = (const float*)d_in[1]; // [1024,64]
    const float* wsg  = (const float*)d_in[2]; // [1024,1]
    const float* wsgu = (const float*)d_in[3]; // [1024,4096]
    const float* wsd  = (const float*)d_in[4]; // [2048,1024]
    const float* wegu = (const float*)d_in[5]; // [64,1024,1024]
    const float* wed  = (const float*)d_in[6]; // [64,512,1024]
    float* out = (float*)d_out;

    float* sact; cudaGetSymbolAddress((void**)&sact, g_shared_act);
    float* eact; cudaGetSymbolAddress((void**)&eact, g_act);
    float* obuf; cudaGetSymbolAddress((void**)&obuf, g_outbuf);
    float* sg;   cudaGetSymbolAddress((void**)&sg,   g_sg);
    int*   cnts; cudaGetSymbolAddress((void**)&cnts, g_counts);
    int*   etok; cudaGetSymbolAddress((void**)&etok, g_expert_tok);

    // 1. zero counts
    zero_counts_kernel<<<1, 64>>>();

    // 2. router + dispatch + shared sigmoid gate
    router_kernel<<<T_TOK, 256>>>(x, wg, wsg);

    // 3a. shared gate_up + swiglu:   [2048,1024]@[1024,2*2048] -> act [2048,2048]
    gemm_swiglu_kernel<<<dim3(ISH / BN, T_TOK / BM, 1), 256>>>(
        x, wsgu, nullptr, nullptr, sact,
        HDIM, ISH, 2 * ISH, ISH, 0, 0, T_TOK, 0);

    // 3b. expert gate_up + swiglu (gathered rows): per-expert [cnt,1024]@[1024,2*512]
    gemm_swiglu_kernel<<<dim3(IDIM / BN, CAP / BM, NEXP), 256>>>(
        x, wegu, etok, cnts, eact,
        HDIM, IDIM, 2 * IDIM, IDIM,
        (long long)HDIM * 2 * IDIM, (long long)CAP * IDIM, 0, CAP);

    // 4a. shared down (row-scaled by sigmoid gate) -> d_out
    gemm_down_kernel<<<dim3(HDIM / BN, T_TOK / BM, 1), 256>>>(
        sact, wsd, out, nullptr, sg,
        ISH, HDIM, 0, 0, 0, T_TOK, 0);

    // 4b. expert down -> outbuf
    gemm_down_kernel<<<dim3(HDIM / BN, CAP / BM, NEXP), 256>>>(
        eact, wed, obuf, cnts, nullptr,
        IDIM, HDIM,
        (long long)CAP * IDIM, (long long)IDIM * HDIM, (long long)CAP * HDIM, 0, CAP);

    // 5. combine expert contributions into d_out
    combine_kernel<<<T_TOK, 256>>>(out);

    (void)in_sizes; (void)n_in; (void)out_size;
}

// round 7
// speedup vs baseline: 2.2522x; 2.2522x over previous
#include <cuda_runtime.h>
#include <cuda_bf16.h>
#include <cstdint>

// ---------------- problem constants ----------------
#define T_TOK   2048
#define HDIM    1024
#define NEXP    64
#define IDIM    512
#define ISH     2048
#define TOPK    8
#define CAP     512

// ---------------- scratch (device globals) ----------------
__device__ float g_sact[(size_t)T_TOK * ISH];        // shared expert activations [2048][2048]
__device__ float g_eact[(size_t)NEXP * CAP * IDIM];  // expert activations [64][512][512]
__device__ float g_sg[T_TOK];
__device__ int   g_counts[NEXP];
__device__ int   g_etok[NEXP * CAP];
__device__ float g_slotw[NEXP * CAP];

// ---------------- helpers ----------------
__device__ __forceinline__ float tf32r(float x) {
    uint32_t d;
    asm("cvt.rna.tf32.f32 %0, %1;" : "=r"(d) : "f"(x));
    return __uint_as_float(d);
}
__device__ __forceinline__ float4 tf32r4(float4 v) {
    v.x = tf32r(v.x); v.y = tf32r(v.y); v.z = tf32r(v.z); v.w = tf32r(v.w);
    return v;
}
// m16n8k8 tf32 mma:  D = A(16x8,row) * B(8x8,col) + D   (fp32 accum)
__device__ __forceinline__ void mma8(float* c, const uint32_t* a, const uint32_t* b) {
    asm volatile(
        "mma.sync.aligned.m16n8k8.row.col.f32.tf32.tf32.f32 "
        "{%0,%1,%2,%3}, {%4,%5,%6,%7}, {%8,%9}, {%0,%1,%2,%3};"
        : "+f"(c[0]), "+f"(c[1]), "+f"(c[2]), "+f"(c[3])
        : "r"(a[0]), "r"(a[1]), "r"(a[2]), "r"(a[3]), "r"(b[0]), "r"(b[1]));
}
__device__ __forceinline__ float silu_mul(float g, float u) {
    return g / (1.f + __expf(-g)) * u;
}

// smem strides (floats), padded for conflict-free fragment LDS
#define AS_STR 20   // BK(16)+4 : bank = (20*g4 + l4) % 32 -> all distinct
#define BS_STR 72   // BN(64)+8 : bank = (8*l4 + g4) % 32  -> all distinct

// ---------------- misc kernels ----------------
__global__ void zero_counts_kernel() {
    if (threadIdx.x < NEXP) g_counts[threadIdx.x] = 0;
}

// ---------------- router (fp32, exact top-k) ----------------
__global__ void router_kernel(const float* __restrict__ X,
                              const float* __restrict__ Wg,
                              const float* __restrict__ Wsg)
{
    __shared__ float xs[HDIM];
    __shared__ float red[256];
    __shared__ float logits[NEXP];

    const int t   = blockIdx.x;
    const int tid = threadIdx.x;
    const float* x = X + (size_t)t * HDIM;

    for (int i = tid; i < HDIM; i += 256) xs[i] = x[i];
    __syncthreads();

    {
        const int e = tid >> 2, r = tid & 3;
        float s = 0.f;
        for (int k = r; k < HDIM; k += 4) s += xs[k] * Wg[k * NEXP + e];
        s += __shfl_down_sync(0xffffffffu, s, 2);
        s += __shfl_down_sync(0xffffffffu, s, 1);
        if (r == 0) logits[e] = s;
    }
    {
        float p = 0.f;
        for (int k = tid; k < HDIM; k += 256) p += xs[k] * Wsg[k];
        red[tid] = p;
    }
    __syncthreads();

    if (tid == 0) {
        float tot = 0.f;
        for (int i = 0; i < 256; i++) tot += red[i];
        g_sg[t] = 1.f / (1.f + __expf(-tot));

        float mx = logits[0];
        for (int i = 1; i < NEXP; i++) mx = fmaxf(mx, logits[i]);
        float pr[NEXP];
        float Z = 0.f;
        for (int i = 0; i < NEXP; i++) { pr[i] = __expf(logits[i] - mx); Z += pr[i]; }

        int   eidx[TOPK];
        float wv[TOPK];
        float wsum = 0.f;
        for (int k = 0; k < TOPK; k++) {
            int best = 0; float bv = -1.f;
            for (int i = 0; i < NEXP; i++) if (pr[i] > bv) { bv = pr[i]; best = i; }
            eidx[k] = best; wv[k] = bv / Z; pr[best] = -1.f;
            wsum += wv[k];
        }
        for (int k = 0; k < TOPK; k++) {
            const float w = wv[k] / wsum;
            const int   e = eidx[k];
            const int slot = atomicAdd(&g_counts[e], 1);
            if (slot < CAP) {
                g_etok[e * CAP + slot]  = t;
                g_slotw[e * CAP + slot] = w;
            }
        }
    }
}

// ---------------- gate_up + SwiGLU (tf32 mma.sync) ----------------
// CTA: 128 rows x 64 act-cols.  B layout [K=1024][2*Nh] (gate cols [0,Nh), up [Nh,2Nh)).
// C[g][m][n] = silu(A.Bg)*(A.Bu),  A rows gathered via rl for experts.
__global__ void __launch_bounds__(256)
k_gateup(const float* __restrict__ A, const int* __restrict__ rl,
         const int* __restrict__ counts, const float* __restrict__ B,
         float* __restrict__ C, int Nh,
         long long bstride, long long cstride, int Mfixed)
{
    const int g  = blockIdx.z;
    const int Mg = counts ? min(counts[g], CAP) : Mfixed;
    const int m0 = blockIdx.y * 128;
    if (m0 >= Mg) return;
    const int n0 = blockIdx.x * 64;
    const int ldb = 2 * Nh;

    const float* Bg0 = B + (size_t)g * bstride;
    float* Cg = C + (size_t)g * cstride;
    const int* rlg = rl ? (rl + g * CAP) : nullptr;

    __shared__ float As[2][128 * AS_STR];
    __shared__ float Bgs[2][16 * BS_STR];
    __shared__ float Bus[2][16 * BS_STR];

    const int tid = threadIdx.x;
    // A loader: 2 float4 per thread (rows tid>>2 and +64, k-quad tid&3)
    const int arow = tid >> 2, aq = tid & 3;
    const float* ap0 = nullptr; const float* ap1 = nullptr;
    {
        int m = m0 + arow;
        if (m < Mg) { int s = rlg ? rlg[m] : m; ap0 = A + (size_t)s * HDIM + aq * 4; }
        m = m0 + arow + 64;
        if (m < Mg) { int s = rlg ? rlg[m] : m; ap1 = A + (size_t)s * HDIM + aq * 4; }
    }
    // B loader: 1 float4 gate + 1 float4 up per thread
    const int bk = tid >> 4, bc = (tid & 15) * 4;
    const float* bgp = Bg0 + (size_t)bk * ldb + n0 + bc;
    const float* bup = bgp + Nh;

    const float4 z4 = make_float4(0.f, 0.f, 0.f, 0.f);

    // preload chunk 0
    {
        float4 a0 = ap0 ? tf32r4(*(const float4*)ap0) : z4;
        float4 a1 = ap1 ? tf32r4(*(const float4*)ap1) : z4;
        float4 bg = tf32r4(*(const float4*)bgp);
        float4 bu = tf32r4(*(const float4*)bup);
        *(float4*)&As[0][arow * AS_STR + aq * 4] = a0;
        *(float4*)&As[0][(arow + 64) * AS_STR + aq * 4] = a1;
        *(float4*)&Bgs[0][bk * BS_STR + bc] = bg;
        *(float4*)&Bus[0][bk * BS_STR + bc] = bu;
    }
    __syncthreads();

    const int w = tid >> 5, lane = tid & 31;
    const int warpM = (w >> 1) * 32, warpN = (w & 1) * 32;
    const int g4 = lane >> 2, l4 = lane & 3;

    float accG[2][4][4]; float accU[2][4][4];
    #pragma unroll
    for (int i = 0; i < 2; i++)
        #pragma unroll
        for (int j = 0; j < 4; j++)
            #pragma unroll
            for (int q = 0; q < 4; q++) { accG[i][j][q] = 0.f; accU[i][j][q] = 0.f; }

    const int NKB = HDIM / 16;   // 64
    for (int kb = 0; kb < NKB; ++kb) {
        const int buf = kb & 1;
        float4 pa0, pa1, pbg, pbu;
        const bool more = (kb + 1 < NKB);
        if (more) {
            const int ko = (kb + 1) * 16;
            pa0 = ap0 ? tf32r4(*(const float4*)(ap0 + ko)) : z4;
            pa1 = ap1 ? tf32r4(*(const float4*)(ap1 + ko)) : z4;
            pbg = tf32r4(*(const float4*)(bgp + (size_t)ko * ldb));
            pbu = tf32r4(*(const float4*)(bup + (size_t)ko * ldb));
        }

        #pragma unroll
        for (int ks = 0; ks < 2; ++ks) {
            const int kk = ks * 8;
            uint32_t af[2][4];
            #pragma unroll
            for (int mt = 0; mt < 2; ++mt) {
                const int r = warpM + mt * 16 + g4;
                af[mt][0] = __float_as_uint(As[buf][r * AS_STR + kk + l4]);
                af[mt][1] = __float_as_uint(As[buf][(r + 8) * AS_STR + kk + l4]);
                af[mt][2] = __float_as_uint(As[buf][r * AS_STR + kk + l4 + 4]);
                af[mt][3] = __float_as_uint(As[buf][(r + 8) * AS_STR + kk + l4 + 4]);
            }
            uint32_t bgf[4][2], buf2[4][2];
            #pragma unroll
            for (int nt = 0; nt < 4; ++nt) {
                const int c = warpN + nt * 8 + g4;
                bgf[nt][0] = __float_as_uint(Bgs[buf][(kk + l4) * BS_STR + c]);
                bgf[nt][1] = __float_as_uint(Bgs[buf][(kk + l4 + 4) * BS_STR + c]);
                buf2[nt][0] = __float_as_uint(Bus[buf][(kk + l4) * BS_STR + c]);
                buf2[nt][1] = __float_as_uint(Bus[buf][(kk + l4 + 4) * BS_STR + c]);
            }
            #pragma unroll
            for (int mt = 0; mt < 2; ++mt)
                #pragma unroll
                for (int nt = 0; nt < 4; ++nt) {
                    mma8(accG[mt][nt], af[mt], bgf[nt]);
                    mma8(accU[mt][nt], af[mt], buf2[nt]);
                }
        }

        if (more) {
            const int nb = buf ^ 1;
            *(float4*)&As[nb][arow * AS_STR + aq * 4] = pa0;
            *(float4*)&As[nb][(arow + 64) * AS_STR + aq * 4] = pa1;
            *(float4*)&Bgs[nb][bk * BS_STR + bc] = pbg;
            *(float4*)&Bus[nb][bk * BS_STR + bc] = pbu;
            __syncthreads();
        }
    }

    // epilogue: silu(gate)*up
    #pragma unroll
    for (int mt = 0; mt < 2; ++mt)
        #pragma unroll
        for (int rr = 0; rr < 2; ++rr) {
            const int m = m0 + warpM + mt * 16 + g4 + rr * 8;
            if (m >= Mg) continue;
            float* crow = Cg + (size_t)m * Nh + n0 + warpN;
            #pragma unroll
            for (int nt = 0; nt < 4; ++nt) {
                const float ga = accG[mt][nt][rr * 2 + 0];
                const float gb = accG[mt][nt][rr * 2 + 1];
                const float ua = accU[mt][nt][rr * 2 + 0];
                const float ub = accU[mt][nt][rr * 2 + 1];
                float2 v;
                v.x = silu_mul(ga, ua);
                v.y = silu_mul(gb, ub);
                *(float2*)(crow + nt * 8 + l4 * 2) = v;
            }
        }
}

// ---------------- down GEMM (tf32 mma.sync) ----------------
// CTA: 128 rows x 64 cols of out (N total = HDIM).  B layout [K][HDIM].
// mode 0: out[m] = g_sg[m] * acc (plain store).  mode 1: atomicAdd(out[token], w*acc).
__global__ void __launch_bounds__(256)
k_down(const float* __restrict__ A, const float* __restrict__ B,
       float* __restrict__ out, const int* __restrict__ counts,
       int K, long long astride, long long bstride, int Mfixed, int mode)
{
    const int g  = blockIdx.z;
    const int Mg = counts ? min(counts[g], CAP) : Mfixed;
    const int m0 = blockIdx.y * 128;
    if (m0 >= Mg) return;
    const int n0 = blockIdx.x * 64;

    const float* Ag = A + (size_t)g * astride;
    const float* Bg = B + (size_t)g * bstride;

    __shared__ float As[2][128 * AS_STR];
    __shared__ float Bs[2][16 * BS_STR];

    const int tid = threadIdx.x;
    const int arow = tid >> 2, aq = tid & 3;
    const float* ap0 = nullptr; const float* ap1 = nullptr;
    {
        int m = m0 + arow;
        if (m < Mg) ap0 = Ag + (size_t)m * K + aq * 4;
        m = m0 + arow + 64;
        if (m < Mg) ap1 = Ag + (size_t)m * K + aq * 4;
    }
    const int bk = tid >> 4, bc = (tid & 15) * 4;
    const float* bp = Bg + (size_t)bk * HDIM + n0 + bc;

    const float4 z4 = make_float4(0.f, 0.f, 0.f, 0.f);
    {
        float4 a0 = ap0 ? tf32r4(*(const float4*)ap0) : z4;
        float4 a1 = ap1 ? tf32r4(*(const float4*)ap1) : z4;
        float4 bv = tf32r4(*(const float4*)bp);
        *(float4*)&As[0][arow * AS_STR + aq * 4] = a0;
        *(float4*)&As[0][(arow + 64) * AS_STR + aq * 4] = a1;
        *(float4*)&Bs[0][bk * BS_STR + bc] = bv;
    }
    __syncthreads();

    const int w = tid >> 5, lane = tid & 31;
    const int warpM = (w >> 1) * 32, warpN = (w & 1) * 32;
    const int g4 = lane >> 2, l4 = lane & 3;

    float acc[2][4][4];
    #pragma unroll
    for (int i = 0; i < 2; i++)
        #pragma unroll
        for (int j = 0; j < 4; j++)
            #pragma unroll
            for (int q = 0; q < 4; q++) acc[i][j][q] = 0.f;

    const int NKB = K / 16;
    for (int kb = 0; kb < NKB; ++kb) {
        const int buf = kb & 1;
        float4 pa0, pa1, pbv;
        const bool more = (kb + 1 < NKB);
        if (more) {
            const int ko = (kb + 1) * 16;
            pa0 = ap0 ? tf32r4(*(const float4*)(ap0 + ko)) : z4;
            pa1 = ap1 ? tf32r4(*(const float4*)(ap1 + ko)) : z4;
            pbv = tf32r4(*(const float4*)(bp + (size_t)ko * HDIM));
        }

        #pragma unroll
        for (int ks = 0; ks < 2; ++ks) {
            const int kk = ks * 8;
            uint32_t af[2][4];
            #pragma unroll
            for (int mt = 0; mt < 2; ++mt) {
                const int r = warpM + mt * 16 + g4;
                af[mt][0] = __float_as_uint(As[buf][r * AS_STR + kk + l4]);
                af[mt][1] = __float_as_uint(As[buf][(r + 8) * AS_STR + kk + l4]);
                af[mt][2] = __float_as_uint(As[buf][r * AS_STR + kk + l4 + 4]);
                af[mt][3] = __float_as_uint(As[buf][(r + 8) * AS_STR + kk + l4 + 4]);
            }
            uint32_t bf[4][2];
            #pragma unroll
            for (int nt = 0; nt < 4; ++nt) {
                const int c = warpN + nt * 8 + g4;
                bf[nt][0] = __float_as_uint(Bs[buf][(kk + l4) * BS_STR + c]);
                bf[nt][1] = __float_as_uint(Bs[buf][(kk + l4 + 4) * BS_STR + c]);
            }
            #pragma unroll
            for (int mt = 0; mt < 2; ++mt)
                #pragma unroll
                for (int nt = 0; nt < 4; ++nt)
                    mma8(acc[mt][nt], af[mt], bf[nt]);
        }

        if (more) {
            const int nb = buf ^ 1;
            *(float4*)&As[nb][arow * AS_STR + aq * 4] = pa0;
            *(float4*)&As[nb][(arow + 64) * AS_STR + aq * 4] = pa1;
            *(float4*)&Bs[nb][bk * BS_STR + bc] = pbv;
            __syncthreads();
        }
    }

    // epilogue
    #pragma unroll
    for (int mt = 0; mt < 2; ++mt)
        #pragma unroll
        for (int rr = 0; rr < 2; ++rr) {
            const int m = m0 + warpM + mt * 16 + g4 + rr * 8;
            if (m >= Mg) continue;
            float scale;
            float* orow;
            if (mode == 0) {
                scale = g_sg[m];
                orow = out + (size_t)m * HDIM + n0 + warpN;
            } else {
                const int t = g_etok[g * CAP + m];
                scale = g_slotw[g * CAP + m];
                orow = out + (size_t)t * HDIM + n0 + warpN;
            }
            #pragma unroll
            for (int nt = 0; nt < 4; ++nt) {
                const float va = scale * acc[mt][nt][rr * 2 + 0];
                const float vb = scale * acc[mt][nt][rr * 2 + 1];
                const int c = nt * 8 + l4 * 2;
                if (mode == 0) {
                    float2 v; v.x = va; v.y = vb;
                    *(float2*)(orow + c) = v;
                } else {
                    atomicAdd(orow + c, va);
                    atomicAdd(orow + c + 1, vb);
                }
            }
        }
}

// ---------------- host launch ----------------
extern "C" void kernel_launch(void* const* d_in, const int* in_sizes, int n_in,
                              void* d_out, int out_size)
{
    const float* x    = (const float*)d_in[0]; // [2048][1024]
    const float* wg   = (const float*)d_in[1]; // [1024][64]
    const float* wsg  = (const float*)d_in[2]; // [1024][1]
    const float* wsgu = (const float*)d_in[3]; // [1024][4096]
    const float* wsd  = (const float*)d_in[4]; // [2048][1024]
    const float* wegu = (const float*)d_in[5]; // [64][1024][1024]
    const float* wed  = (const float*)d_in[6]; // [64][512][1024]
    float* out = (float*)d_out;

    float* sact; cudaGetSymbolAddress((void**)&sact, g_sact);
    float* eact; cudaGetSymbolAddress((void**)&eact, g_eact);
    int*   cnts; cudaGetSymbolAddress((void**)&cnts, g_counts);
    int*   etok; cudaGetSymbolAddress((void**)&etok, g_etok);

    // 1. routing
    zero_counts_kernel<<<1, 64>>>();
    router_kernel<<<T_TOK, 256>>>(x, wg, wsg);

    // 2. gate_up + SwiGLU
    k_gateup<<<dim3(ISH / 64, T_TOK / 128, 1), 256>>>(
        x, nullptr, nullptr, wsgu, sact, ISH, 0LL, 0LL, T_TOK);
    k_gateup<<<dim3(IDIM / 64, CAP / 128, NEXP), 256>>>(
        x, etok, cnts, wegu, eact, IDIM,
        (long long)HDIM * 2 * IDIM, (long long)CAP * IDIM, 0);

    // 3. down:  shared writes out (sigmoid-gated), experts atomicAdd (router-weighted)
    k_down<<<dim3(HDIM / 64, T_TOK / 128, 1), 256>>>(
        sact, wsd, out, nullptr, ISH, 0LL, 0LL, T_TOK, 0);
    k_down<<<dim3(HDIM / 64, CAP / 128, NEXP), 256>>>(
        eact, wed, out, cnts, IDIM,
        (long long)CAP * IDIM, (long long)IDIM * HDIM, 0, 1);

    (void)in_sizes; (void)n_in; (void)out_size; (void)wsg;
}

// round 8
// speedup vs baseline: 3.2063x; 1.4237x over previous
#include <cuda_runtime.h>
#include <cuda_fp16.h>
#include <cstdint>

// ---------------- problem constants ----------------
#define T_TOK   2048
#define HDIM    1024
#define NEXP    64
#define IDIM    512
#define ISH     2048
#define TOPK    8
#define CAP     512

// ---------------- scratch (device globals) ----------------
__device__ __half g_xh[(size_t)T_TOK * HDIM];            // x as half [2048][1024]
__device__ __half g_sact[(size_t)T_TOK * ISH];           // shared acts half
__device__ __half g_eact[(size_t)NEXP * CAP * IDIM];     // expert acts half
__device__ __half g_wsguT[(size_t)2 * ISH * HDIM];       // [4096][1024]
__device__ __half g_wsdT[(size_t)HDIM * ISH];            // [1024][2048]
__device__ __half g_weguT[(size_t)NEXP * 2 * IDIM * HDIM]; // [64][1024][1024]
__device__ __half g_wedT[(size_t)NEXP * HDIM * IDIM];    // [64][1024][512]
__device__ float  g_sg[T_TOK];
__device__ int    g_counts[NEXP];
__device__ int    g_etok[NEXP * CAP];
__device__ float  g_slotw[NEXP * CAP];

// ---------------- helpers ----------------
// m16n8k16 fp16 mma, fp32 accum
__device__ __forceinline__ void mma16(float* c, const uint32_t* a, const uint32_t* b) {
    asm volatile(
        "mma.sync.aligned.m16n8k16.row.col.f32.f16.f16.f32 "
        "{%0,%1,%2,%3}, {%4,%5,%6,%7}, {%8,%9}, {%0,%1,%2,%3};"
        : "+f"(c[0]), "+f"(c[1]), "+f"(c[2]), "+f"(c[3])
        : "r"(a[0]), "r"(a[1]), "r"(a[2]), "r"(a[3]), "r"(b[0]), "r"(b[1]));
}
__device__ __forceinline__ float silu_mul(float g, float u) {
    return g / (1.f + __expf(-g)) * u;
}

#define AST 40   // smem row stride in halfs (80B): LDS bank = (20*g4+l4)%32, conflict-free

// ---------------- misc kernels ----------------
__global__ void zero_counts_kernel() {
    if (threadIdx.x < NEXP) g_counts[threadIdx.x] = 0;
}

// fp32 -> half elementwise (n multiple of 4)
__global__ void f2h_kernel(const float* __restrict__ in, __half* __restrict__ out, int n) {
    const int i = (blockIdx.x * 256 + threadIdx.x) * 4;
    if (i < n) {
        const float4 v = *(const float4*)(in + i);
        __half2* o = (__half2*)(out + i);
        o[0] = __floats2half2_rn(v.x, v.y);
        o[1] = __floats2half2_rn(v.z, v.w);
    }
}

// transpose + convert:  in [g][K][N] fp32 -> out [g][N][K] half
__global__ void transpose_h_kernel(const float* __restrict__ in, __half* __restrict__ out,
                                   int K, int N) {
    __shared__ float tile[32][33];
    const int g = blockIdx.z;
    const float* ing = in + (size_t)g * K * N;
    __half* outg = out + (size_t)g * K * N;
    const int n0 = blockIdx.x * 32, k0 = blockIdx.y * 32;
    const int tx = threadIdx.x, ty = threadIdx.y;
    #pragma unroll
    for (int i = 0; i < 32; i += 8)
        tile[ty + i][tx] = ing[(size_t)(k0 + ty + i) * N + n0 + tx];
    __syncthreads();
    #pragma unroll
    for (int i = 0; i < 32; i += 8)
        outg[(size_t)(n0 + ty + i) * K + k0 + tx] = __float2half_rn(tile[tx][ty + i]);
}

// ---------------- router (fp32, exact top-k) ----------------
__global__ void router_kernel(const float* __restrict__ X,
                              const float* __restrict__ Wg,
                              const float* __restrict__ Wsg)
{
    __shared__ float xs[HDIM];
    __shared__ float red[256];
    __shared__ float logits[NEXP];

    const int t   = blockIdx.x;
    const int tid = threadIdx.x;
    const float* x = X + (size_t)t * HDIM;

    for (int i = tid; i < HDIM; i += 256) xs[i] = x[i];
    __syncthreads();

    {
        const int e = tid >> 2, r = tid & 3;
        float s = 0.f;
        for (int k = r; k < HDIM; k += 4) s += xs[k] * Wg[k * NEXP + e];
        s += __shfl_down_sync(0xffffffffu, s, 2);
        s += __shfl_down_sync(0xffffffffu, s, 1);
        if (r == 0) logits[e] = s;
    }
    {
        float p = 0.f;
        for (int k = tid; k < HDIM; k += 256) p += xs[k] * Wsg[k];
        red[tid] = p;
    }
    __syncthreads();

    if (tid == 0) {
        float tot = 0.f;
        for (int i = 0; i < 256; i++) tot += red[i];
        g_sg[t] = 1.f / (1.f + __expf(-tot));

        float mx = logits[0];
        for (int i = 1; i < NEXP; i++) mx = fmaxf(mx, logits[i]);
        float pr[NEXP];
        float Z = 0.f;
        for (int i = 0; i < NEXP; i++) { pr[i] = __expf(logits[i] - mx); Z += pr[i]; }

        int   eidx[TOPK];
        float wv[TOPK];
        float wsum = 0.f;
        for (int k = 0; k < TOPK; k++) {
            int best = 0; float bv = -1.f;
            for (int i = 0; i < NEXP; i++) if (pr[i] > bv) { bv = pr[i]; best = i; }
            eidx[k] = best; wv[k] = bv / Z; pr[best] = -1.f;
            wsum += wv[k];
        }
        for (int k = 0; k < TOPK; k++) {
            const float w = wv[k] / wsum;
            const int   e = eidx[k];
            const int slot = atomicAdd(&g_counts[e], 1);
            if (slot < CAP) {
                g_etok[e * CAP + slot]  = t;
                g_slotw[e * CAP + slot] = w;
            }
        }
    }
}

// ---------------- gate_up + SwiGLU (fp16 mma.sync m16n8k16) ----------------
// CTA 128 rows x 64 act-cols.  BT = half [2*Nh][K] K-major (gate rows [0,Nh), up [Nh,2Nh)).
// A = half [*, K], rows gathered via rl for experts.  C = half [*, Nh].
__global__ void __launch_bounds__(256, 2)
k_gateup(const __half* __restrict__ A, const int* __restrict__ rl,
         const int* __restrict__ counts, const __half* __restrict__ BT,
         __half* __restrict__ C, int Nh, int K,
         long long bstride, long long cstride, int Mfixed)
{
    const int g  = blockIdx.z;
    const int Mg = counts ? min(counts[g], CAP) : Mfixed;
    const int m0 = blockIdx.y * 128;
    if (m0 >= Mg) return;
    const int n0 = blockIdx.x * 64;

    const __half* BTg = BT + (size_t)g * bstride;
    __half* Cg = C + (size_t)g * cstride;
    const int* rlg = rl ? (rl + g * CAP) : nullptr;

    __shared__ __half As[2][128 * AST];   // 128 x 32 halfs (+pad)
    __shared__ __half Bs[2][128 * AST];   // rows 0-63 gate, 64-127 up

    const int tid = threadIdx.x;
    // loaders: thread -> tile row tid>>1, half-offset (tid&1)*16 (32B = 2x uint4)
    const int lrow = tid >> 1;
    const int lo16 = (tid & 1) * 16;

    const __half* ap = nullptr;
    {
        const int m = m0 + lrow;
        if (m < Mg) {
            const int s = rlg ? rlg[m] : m;
            ap = A + (size_t)s * K + lo16;
        }
    }
    const int grow = (lrow < 64) ? (n0 + lrow) : (Nh + n0 + lrow - 64);
    const __half* bp = BTg + (size_t)grow * K + lo16;

    const uint4 z4 = make_uint4(0u, 0u, 0u, 0u);

    // preload chunk 0
    {
        uint4 a0 = ap ? *(const uint4*)(ap)     : z4;
        uint4 a1 = ap ? *(const uint4*)(ap + 8) : z4;
        uint4 b0 = *(const uint4*)(bp);
        uint4 b1 = *(const uint4*)(bp + 8);
        *(uint4*)&As[0][lrow * AST + lo16]     = a0;
        *(uint4*)&As[0][lrow * AST + lo16 + 8] = a1;
        *(uint4*)&Bs[0][lrow * AST + lo16]     = b0;
        *(uint4*)&Bs[0][lrow * AST + lo16 + 8] = b1;
    }
    __syncthreads();

    const int w = tid >> 5, lane = tid & 31;
    const int warpM = (w >> 1) * 32, warpN = (w & 1) * 32;
    const int g4 = lane >> 2, l4 = lane & 3;

    float accG[2][4][4]; float accU[2][4][4];
    #pragma unroll
    for (int i = 0; i < 2; i++)
        #pragma unroll
        for (int j = 0; j < 4; j++)
            #pragma unroll
            for (int q = 0; q < 4; q++) { accG[i][j][q] = 0.f; accU[i][j][q] = 0.f; }

    const int NKB = K / 32;
    for (int kb = 0; kb < NKB; ++kb) {
        const int buf = kb & 1;
        uint4 pa0, pa1, pb0, pb1;
        const bool more = (kb + 1 < NKB);
        if (more) {
            const int ko = (kb + 1) * 32;
            pa0 = ap ? *(const uint4*)(ap + ko)     : z4;
            pa1 = ap ? *(const uint4*)(ap + ko + 8) : z4;
            pb0 = *(const uint4*)(bp + ko);
            pb1 = *(const uint4*)(bp + ko + 8);
        }

        #pragma unroll
        for (int ks = 0; ks < 2; ++ks) {
            const int ko = ks * 16;
            uint32_t af[2][4];
            #pragma unroll
            for (int mt = 0; mt < 2; ++mt) {
                const int r = warpM + mt * 16 + g4;
                af[mt][0] = *(const uint32_t*)&As[buf][r * AST + ko + 2 * l4];
                af[mt][1] = *(const uint32_t*)&As[buf][(r + 8) * AST + ko + 2 * l4];
                af[mt][2] = *(const uint32_t*)&As[buf][r * AST + ko + 8 + 2 * l4];
                af[mt][3] = *(const uint32_t*)&As[buf][(r + 8) * AST + ko + 8 + 2 * l4];
            }
            uint32_t bgf[4][2], buf2[4][2];
            #pragma unroll
            for (int nt = 0; nt < 4; ++nt) {
                const int c = warpN + nt * 8 + g4;
                bgf[nt][0]  = *(const uint32_t*)&Bs[buf][c * AST + ko + 2 * l4];
                bgf[nt][1]  = *(const uint32_t*)&Bs[buf][c * AST + ko + 8 + 2 * l4];
                buf2[nt][0] = *(const uint32_t*)&Bs[buf][(64 + c) * AST + ko + 2 * l4];
                buf2[nt][1] = *(const uint32_t*)&Bs[buf][(64 + c) * AST + ko + 8 + 2 * l4];
            }
            #pragma unroll
            for (int mt = 0; mt < 2; ++mt)
                #pragma unroll
                for (int nt = 0; nt < 4; ++nt) {
                    mma16(accG[mt][nt], af[mt], bgf[nt]);
                    mma16(accU[mt][nt], af[mt], buf2[nt]);
                }
        }

        if (more) {
            const int nb = buf ^ 1;
            *(uint4*)&As[nb][lrow * AST + lo16]     = pa0;
            *(uint4*)&As[nb][lrow * AST + lo16 + 8] = pa1;
            *(uint4*)&Bs[nb][lrow * AST + lo16]     = pb0;
            *(uint4*)&Bs[nb][lrow * AST + lo16 + 8] = pb1;
            __syncthreads();
        }
    }

    // epilogue: silu(gate)*up -> half
    #pragma unroll
    for (int mt = 0; mt < 2; ++mt)
        #pragma unroll
        for (int rr = 0; rr < 2; ++rr) {
            const int m = m0 + warpM + mt * 16 + g4 + rr * 8;
            if (m >= Mg) continue;
            __half* crow = Cg + (size_t)m * Nh + n0 + warpN;
            #pragma unroll
            for (int nt = 0; nt < 4; ++nt) {
                const float va = silu_mul(accG[mt][nt][rr * 2 + 0], accU[mt][nt][rr * 2 + 0]);
                const float vb = silu_mul(accG[mt][nt][rr * 2 + 1], accU[mt][nt][rr * 2 + 1]);
                *(__half2*)(crow + nt * 8 + 2 * l4) = __floats2half2_rn(va, vb);
            }
        }
}

// ---------------- down GEMM (fp16 mma.sync) ----------------
// CTA 128 rows x 128 out-cols.  BT = half [HDIM][K] K-major.  A = half [*, K].
// mode 0: out[m] = g_sg[m]*acc (store).  mode 1: atomicAdd(out[token], w*acc).
__global__ void __launch_bounds__(256, 2)
k_down(const __half* __restrict__ A, const __half* __restrict__ BT,
       float* __restrict__ out, const int* __restrict__ counts,
       int K, long long astride, long long bstride, int Mfixed, int mode)
{
    const int g  = blockIdx.z;
    const int Mg = counts ? min(counts[g], CAP) : Mfixed;
    const int m0 = blockIdx.y * 128;
    if (m0 >= Mg) return;
    const int n0 = blockIdx.x * 128;

    const __half* Ag  = A + (size_t)g * astride;
    const __half* BTg = BT + (size_t)g * bstride;

    __shared__ __half As[2][128 * AST];
    __shared__ __half Bs[2][128 * AST];

    const int tid = threadIdx.x;
    const int lrow = tid >> 1;
    const int lo16 = (tid & 1) * 16;

    const __half* ap = nullptr;
    if (m0 + lrow < Mg) ap = Ag + (size_t)(m0 + lrow) * K + lo16;
    const __half* bp = BTg + (size_t)(n0 + lrow) * K + lo16;

    const uint4 z4 = make_uint4(0u, 0u, 0u, 0u);
    {
        uint4 a0 = ap ? *(const uint4*)(ap)     : z4;
        uint4 a1 = ap ? *(const uint4*)(ap + 8) : z4;
        uint4 b0 = *(const uint4*)(bp);
        uint4 b1 = *(const uint4*)(bp + 8);
        *(uint4*)&As[0][lrow * AST + lo16]     = a0;
        *(uint4*)&As[0][lrow * AST + lo16 + 8] = a1;
        *(uint4*)&Bs[0][lrow * AST + lo16]     = b0;
        *(uint4*)&Bs[0][lrow * AST + lo16 + 8] = b1;
    }
    __syncthreads();

    const int w = tid >> 5, lane = tid & 31;
    const int warpM = (w >> 1) * 32, warpN = (w & 1) * 64;
    const int g4 = lane >> 2, l4 = lane & 3;

    float acc[2][8][4];
    #pragma unroll
    for (int i = 0; i < 2; i++)
        #pragma unroll
        for (int j = 0; j < 8; j++)
            #pragma unroll
            for (int q = 0; q < 4; q++) acc[i][j][q] = 0.f;

    const int NKB = K / 32;
    for (int kb = 0; kb < NKB; ++kb) {
        const int buf = kb & 1;
        uint4 pa0, pa1, pb0, pb1;
        const bool more = (kb + 1 < NKB);
        if (more) {
            const int ko = (kb + 1) * 32;
            pa0 = ap ? *(const uint4*)(ap + ko)     : z4;
            pa1 = ap ? *(const uint4*)(ap + ko + 8) : z4;
            pb0 = *(const uint4*)(bp + ko);
            pb1 = *(const uint4*)(bp + ko + 8);
        }

        #pragma unroll
        for (int ks = 0; ks < 2; ++ks) {
            const int ko = ks * 16;
            uint32_t af[2][4];
            #pragma unroll
            for (int mt = 0; mt < 2; ++mt) {
                const int r = warpM + mt * 16 + g4;
                af[mt][0] = *(const uint32_t*)&As[buf][r * AST + ko + 2 * l4];
                af[mt][1] = *(const uint32_t*)&As[buf][(r + 8) * AST + ko + 2 * l4];
                af[mt][2] = *(const uint32_t*)&As[buf][r * AST + ko + 8 + 2 * l4];
                af[mt][3] = *(const uint32_t*)&As[buf][(r + 8) * AST + ko + 8 + 2 * l4];
            }
            uint32_t bf[8][2];
            #pragma unroll
            for (int nt = 0; nt < 8; ++nt) {
                const int c = warpN + nt * 8 + g4;
                bf[nt][0] = *(const uint32_t*)&Bs[buf][c * AST + ko + 2 * l4];
                bf[nt][1] = *(const uint32_t*)&Bs[buf][c * AST + ko + 8 + 2 * l4];
            }
            #pragma unroll
            for (int mt = 0; mt < 2; ++mt)
                #pragma unroll
                for (int nt = 0; nt < 8; ++nt)
                    mma16(acc[mt][nt], af[mt], bf[nt]);
        }

        if (more) {
            const int nb = buf ^ 1;
            *(uint4*)&As[nb][lrow * AST + lo16]     = pa0;
            *(uint4*)&As[nb][lrow * AST + lo16 + 8] = pa1;
            *(uint4*)&Bs[nb][lrow * AST + lo16]     = pb0;
            *(uint4*)&Bs[nb][lrow * AST + lo16 + 8] = pb1;
            __syncthreads();
        }
    }

    // epilogue
    #pragma unroll
    for (int mt = 0; mt < 2; ++mt)
        #pragma unroll
        for (int rr = 0; rr < 2; ++rr) {
            const int m = m0 + warpM + mt * 16 + g4 + rr * 8;
            if (m >= Mg) continue;
            float scale;
            float* orow;
            if (mode == 0) {
                scale = g_sg[m];
                orow = out + (size_t)m * HDIM + n0 + warpN;
            } else {
                const int t = g_etok[g * CAP + m];
                scale = g_slotw[g * CAP + m];
                orow = out + (size_t)t * HDIM + n0 + warpN;
            }
            #pragma unroll
            for (int nt = 0; nt < 8; ++nt) {
                const float va = scale * acc[mt][nt][rr * 2 + 0];
                const float vb = scale * acc[mt][nt][rr * 2 + 1];
                const int c = nt * 8 + 2 * l4;
                if (mode == 0) {
                    float2 v; v.x = va; v.y = vb;
                    *(float2*)(orow + c) = v;
                } else {
                    atomicAdd(orow + c, va);
                    atomicAdd(orow + c + 1, vb);
                }
            }
        }
}

// ---------------- host launch ----------------
extern "C" void kernel_launch(void* const* d_in, const int* in_sizes, int n_in,
                              void* d_out, int out_size)
{
    const float* x    = (const float*)d_in[0]; // [2048][1024]
    const float* wg   = (const float*)d_in[1]; // [1024][64]
    const float* wsg  = (const float*)d_in[2]; // [1024][1]
    const float* wsgu = (const float*)d_in[3]; // [1024][4096]
    const float* wsd  = (const float*)d_in[4]; // [2048][1024]
    const float* wegu = (const float*)d_in[5]; // [64][1024][1024]
    const float* wed  = (const float*)d_in[6]; // [64][512][1024]
    float* out = (float*)d_out;

    __half* xh;    cudaGetSymbolAddress((void**)&xh,    g_xh);
    __half* sact;  cudaGetSymbolAddress((void**)&sact,  g_sact);
    __half* eact;  cudaGetSymbolAddress((void**)&eact,  g_eact);
    __half* wsguT; cudaGetSymbolAddress((void**)&wsguT, g_wsguT);
    __half* wsdT;  cudaGetSymbolAddress((void**)&wsdT,  g_wsdT);
    __half* weguT; cudaGetSymbolAddress((void**)&weguT, g_weguT);
    __half* wedT;  cudaGetSymbolAddress((void**)&wedT,  g_wedT);
    int*    cnts;  cudaGetSymbolAddress((void**)&cnts,  g_counts);
    int*    etok;  cudaGetSymbolAddress((void**)&etok,  g_etok);

    // 1. routing (fp32 exact)
    zero_counts_kernel<<<1, 64>>>();
    router_kernel<<<T_TOK, 256>>>(x, wg, wsg);

    // 2. pre-pass: convert x, transpose+convert weights to half K-major
    f2h_kernel<<<(T_TOK * HDIM / 4 + 255) / 256, 256>>>(x, xh, T_TOK * HDIM);
    dim3 tb(32, 8);
    transpose_h_kernel<<<dim3(4096 / 32, 1024 / 32, 1),  tb>>>(wsgu, wsguT, 1024, 4096);
    transpose_h_kernel<<<dim3(1024 / 32, 2048 / 32, 1),  tb>>>(wsd,  wsdT,  2048, 1024);
    transpose_h_kernel<<<dim3(1024 / 32, 1024 / 32, 64), tb>>>(wegu, weguT, 1024, 1024);
    transpose_h_kernel<<<dim3(1024 / 32,  512 / 32, 64), tb>>>(wed,  wedT,   512, 1024);

    // 3. gate_up + SwiGLU
    k_gateup<<<dim3(ISH / 64, T_TOK / 128, 1), 256>>>(
        xh, nullptr, nullptr, wsguT, sact, ISH, HDIM, 0LL, 0LL, T_TOK);
    k_gateup<<<dim3(IDIM / 64, CAP / 128, NEXP), 256>>>(
        xh, etok, cnts, weguT, eact, IDIM, HDIM,
        (long long)(2 * IDIM) * HDIM, (long long)CAP * IDIM, 0);

    // 4. down: shared writes out (sigmoid-gated), experts atomicAdd (router-weighted)
    k_down<<<dim3(HDIM / 128, T_TOK / 128, 1), 256>>>(
        sact, wsdT, out, nullptr, ISH, 0LL, 0LL, T_TOK, 0);
    k_down<<<dim3(HDIM / 128, CAP / 128, NEXP), 256>>>(
        eact, wedT, out, cnts, IDIM,
        (long long)CAP * IDIM, (long long)HDIM * IDIM, 0, 1);

    (void)in_sizes; (void)n_in; (void)out_size; (void)wsg;
}

// round 10
// speedup vs baseline: 4.1165x; 1.2839x over previous
#include <cuda_runtime.h>
#include <cuda_fp16.h>
#include <cstdint>

// ---------------- problem constants ----------------
#define T_TOK   2048
#define HDIM    1024
#define NEXP    64
#define IDIM    512
#define ISH     2048
#define TOPK    8
#define CAP     512

// ---------------- scratch (device globals) ----------------
__device__ __half g_xh[(size_t)T_TOK * HDIM];            // x as half
__device__ __half g_sact[(size_t)T_TOK * ISH];           // shared acts half
__device__ __half g_eact[(size_t)NEXP * CAP * IDIM];     // expert acts half
__device__ float  g_sg[T_TOK];
__device__ int    g_counts[NEXP];
__device__ int    g_etok[NEXP * CAP];
__device__ float  g_slotw[NEXP * CAP];

// ---------------- helpers ----------------
__device__ __forceinline__ uint32_t smem_u32(const void* p) {
    uint32_t a;
    asm("{ .reg .u64 t; cvta.to.shared.u64 t, %1; cvt.u32.u64 %0, t; }" : "=r"(a) : "l"(p));
    return a;
}
// m16n8k16 fp16 mma, fp32 accum
__device__ __forceinline__ void mma16(float* c, const uint32_t* a, const uint32_t* b) {
    asm volatile(
        "mma.sync.aligned.m16n8k16.row.col.f32.f16.f16.f32 "
        "{%0,%1,%2,%3}, {%4,%5,%6,%7}, {%8,%9}, {%0,%1,%2,%3};"
        : "+f"(c[0]), "+f"(c[1]), "+f"(c[2]), "+f"(c[3])
        : "r"(a[0]), "r"(a[1]), "r"(a[2]), "r"(a[3]), "r"(b[0]), "r"(b[1]));
}
__device__ __forceinline__ void ldsm_x4(uint32_t* r, uint32_t addr) {
    asm volatile("ldmatrix.sync.aligned.m8n8.x4.shared.b16 {%0,%1,%2,%3}, [%4];"
                 : "=r"(r[0]), "=r"(r[1]), "=r"(r[2]), "=r"(r[3]) : "r"(addr));
}
__device__ __forceinline__ void ldsm_x4t(uint32_t* r, uint32_t addr) {
    asm volatile("ldmatrix.sync.aligned.m8n8.x4.trans.shared.b16 {%0,%1,%2,%3}, [%4];"
                 : "=r"(r[0]), "=r"(r[1]), "=r"(r[2]), "=r"(r[3]) : "r"(addr));
}
__device__ __forceinline__ uint4 f8_to_h8(float4 a, float4 b) {
    uint4 r; __half2 h;
    h = __floats2half2_rn(a.x, a.y); r.x = *(uint32_t*)&h;
    h = __floats2half2_rn(a.z, a.w); r.y = *(uint32_t*)&h;
    h = __floats2half2_rn(b.x, b.y); r.z = *(uint32_t*)&h;
    h = __floats2half2_rn(b.z, b.w); r.w = *(uint32_t*)&h;
    return r;
}
__device__ __forceinline__ float silu_mul(float g, float u) {
    return g / (1.f + __expf(-g)) * u;
}

#define AST 40    // A smem row stride (halfs): 80B -> ldmatrix rows hit banks 20r%32, distinct
#define BST 136   // B smem row stride (halfs): 272B -> k-rows hit 16B-groups 17k%8, optimal
#define ABYTES (128 * AST * 2)
#define BBYTES (32 * BST * 2)

// ---------------- misc kernels ----------------
__global__ void zero_counts_kernel() {
    if (threadIdx.x < NEXP) g_counts[threadIdx.x] = 0;
}

__global__ void f2h_kernel(const float* __restrict__ in, __half* __restrict__ out, int n) {
    const int i = (blockIdx.x * 256 + threadIdx.x) * 4;
    if (i < n) {
        const float4 v = *(const float4*)(in + i);
        __half2* o = (__half2*)(out + i);
        o[0] = __floats2half2_rn(v.x, v.y);
        o[1] = __floats2half2_rn(v.z, v.w);
    }
}

// ---------------- router (fp32, exact top-k) ----------------
__global__ void router_kernel(const float* __restrict__ X,
                              const float* __restrict__ Wg,
                              const float* __restrict__ Wsg)
{
    __shared__ float xs[HDIM];
    __shared__ float red[256];
    __shared__ float logits[NEXP];

    const int t   = blockIdx.x;
    const int tid = threadIdx.x;
    const float* x = X + (size_t)t * HDIM;

    for (int i = tid; i < HDIM; i += 256) xs[i] = x[i];
    __syncthreads();

    {
        const int e = tid >> 2, r = tid & 3;
        float s = 0.f;
        for (int k = r; k < HDIM; k += 4) s += xs[k] * Wg[k * NEXP + e];
        s += __shfl_down_sync(0xffffffffu, s, 2);
        s += __shfl_down_sync(0xffffffffu, s, 1);
        if (r == 0) logits[e] = s;
    }
    {
        float p = 0.f;
        for (int k = tid; k < HDIM; k += 256) p += xs[k] * Wsg[k];
        red[tid] = p;
    }
    __syncthreads();

    if (tid == 0) {
        float tot = 0.f;
        for (int i = 0; i < 256; i++) tot += red[i];
        g_sg[t] = 1.f / (1.f + __expf(-tot));

        float mx = logits[0];
        for (int i = 1; i < NEXP; i++) mx = fmaxf(mx, logits[i]);
        float pr[NEXP];
        float Z = 0.f;
        for (int i = 0; i < NEXP; i++) { pr[i] = __expf(logits[i] - mx); Z += pr[i]; }

        int   eidx[TOPK];
        float wv[TOPK];
        float wsum = 0.f;
        for (int k = 0; k < TOPK; k++) {
            int best = 0; float bv = -1.f;
            for (int i = 0; i < NEXP; i++) if (pr[i] > bv) { bv = pr[i]; best = i; }
            eidx[k] = best; wv[k] = bv / Z; pr[best] = -1.f;
            wsum += wv[k];
        }
        for (int k = 0; k < TOPK; k++) {
            const float w = wv[k] / wsum;
            const int   e = eidx[k];
            const int slot = atomicAdd(&g_counts[e], 1);
            if (slot < CAP) {
                g_etok[e * CAP + slot]  = t;
                g_slotw[e * CAP + slot] = w;
            }
        }
    }
}

// ---------------- gate_up + SwiGLU (fp16 mma + ldmatrix, fp32 B direct) ----------------
// CTA 128 rows x 64 act-cols.  B = fp32 [K][2*Nh] natural layout (gate [0,Nh), up [Nh,2Nh)).
// A = half [*, K] rows gathered via rl.  C = half [*, Nh].
__global__ void __launch_bounds__(256, 2)
k_gateup(const __half* __restrict__ A, const int* __restrict__ rl,
         const int* __restrict__ counts, const float* __restrict__ B,
         __half* __restrict__ C, int Nh, int K,
         long long bstride, long long cstride, int Mfixed)
{
    const int g  = blockIdx.z;
    const int Mg = counts ? min(counts[g], CAP) : Mfixed;
    const int m0 = blockIdx.y * 128;
    if (m0 >= Mg) return;
    const int n0 = blockIdx.x * 64;
    const int ldb = 2 * Nh;

    const float* Bg = B + (size_t)g * bstride;
    __half* Cg = C + (size_t)g * cstride;
    const int* rlg = rl ? (rl + g * CAP) : nullptr;

    __shared__ __half As[2][128 * AST];   // [m][k] natural
    __shared__ __half Bs[2][32 * BST];    // [k][n] natural: cols 0-63 gate, 64-127 up

    const int tid = threadIdx.x;

    // A loader: row tid>>1, 2x uint4 (32 halfs)
    const int lrow = tid >> 1;
    const int lo16 = (tid & 1) * 16;
    const __half* ap = nullptr;
    {
        const int m = m0 + lrow;
        if (m < Mg) { const int s = rlg ? rlg[m] : m; ap = A + (size_t)s * K + lo16; }
    }
    // B loader: chunk bc (0-15 -> 8-col groups; <8 gate, >=8 up), rows bk and bk+16
    const int bc = tid & 15;
    const int bk = tid >> 4;
    const int bcol = (bc < 8) ? (n0 + bc * 8) : (Nh + n0 + (bc - 8) * 8);
    const float* bp = Bg + (size_t)bk * ldb + bcol;
    const int bsc = bc * 8;  // local smem col

    const uint4 z4 = make_uint4(0u, 0u, 0u, 0u);

    // preload chunk 0
    {
        uint4 a0 = ap ? *(const uint4*)(ap)     : z4;
        uint4 a1 = ap ? *(const uint4*)(ap + 8) : z4;
        float4 q0 = *(const float4*)(bp);
        float4 q1 = *(const float4*)(bp + 4);
        float4 q2 = *(const float4*)(bp + (size_t)16 * ldb);
        float4 q3 = *(const float4*)(bp + (size_t)16 * ldb + 4);
        *(uint4*)&As[0][lrow * AST + lo16]     = a0;
        *(uint4*)&As[0][lrow * AST + lo16 + 8] = a1;
        *(uint4*)&Bs[0][bk * BST + bsc]        = f8_to_h8(q0, q1);
        *(uint4*)&Bs[0][(bk + 16) * BST + bsc] = f8_to_h8(q2, q3);
    }
    __syncthreads();

    const int w = tid >> 5, lane = tid & 31;
    const int warpM = (w >> 1) * 32, warpN = (w & 1) * 32;

    // ldmatrix lane addresses
    const uint32_t as_u = smem_u32(As);
    const uint32_t bs_u = smem_u32(Bs);
    const uint32_t a_lm = as_u + (uint32_t)(((warpM + (lane & 15)) * AST + ((lane >> 4) * 8)) * 2);
    const uint32_t b_lm = bs_u + (uint32_t)((((lane & 15)) * BST + warpN + ((lane >> 4) * 8)) * 2);

    float accG[2][4][4]; float accU[2][4][4];
    #pragma unroll
    for (int i = 0; i < 2; i++)
        #pragma unroll
        for (int j = 0; j < 4; j++)
            #pragma unroll
            for (int q = 0; q < 4; q++) { accG[i][j][q] = 0.f; accU[i][j][q] = 0.f; }

    const int NKB = K / 32;
    for (int kb = 0; kb < NKB; ++kb) {
        const int buf = kb & 1;
        uint4 pa0, pa1;
        float4 q0, q1, q2, q3;
        const bool more = (kb + 1 < NKB);
        if (more) {
            const int ko = (kb + 1) * 32;
            pa0 = ap ? *(const uint4*)(ap + ko)     : z4;
            pa1 = ap ? *(const uint4*)(ap + ko + 8) : z4;
            q0 = *(const float4*)(bp + (size_t)ko * ldb);
            q1 = *(const float4*)(bp + (size_t)ko * ldb + 4);
            q2 = *(const float4*)(bp + (size_t)(ko + 16) * ldb);
            q3 = *(const float4*)(bp + (size_t)(ko + 16) * ldb + 4);
        }

        const uint32_t abase = a_lm + buf * ABYTES;
        const uint32_t bbase = b_lm + buf * BBYTES;
        #pragma unroll
        for (int ks = 0; ks < 2; ++ks) {
            uint32_t af[2][4];
            ldsm_x4(af[0], abase + ks * 32);
            ldsm_x4(af[1], abase + 16 * AST * 2 + ks * 32);
            uint32_t bgf[4][2], buf2[4][2], t[4];
            const uint32_t brow = bbase + ks * 16 * BST * 2;
            ldsm_x4t(t, brow);
            bgf[0][0] = t[0]; bgf[0][1] = t[1]; bgf[1][0] = t[2]; bgf[1][1] = t[3];
            ldsm_x4t(t, brow + 32);
            bgf[2][0] = t[0]; bgf[2][1] = t[1]; bgf[3][0] = t[2]; bgf[3][1] = t[3];
            ldsm_x4t(t, brow + 128);
            buf2[0][0] = t[0]; buf2[0][1] = t[1]; buf2[1][0] = t[2]; buf2[1][1] = t[3];
            ldsm_x4t(t, brow + 128 + 32);
            buf2[2][0] = t[0]; buf2[2][1] = t[1]; buf2[3][0] = t[2]; buf2[3][1] = t[3];
            #pragma unroll
            for (int mt = 0; mt < 2; ++mt)
                #pragma unroll
                for (int nt = 0; nt < 4; ++nt) {
                    mma16(accG[mt][nt], af[mt], bgf[nt]);
                    mma16(accU[mt][nt], af[mt], buf2[nt]);
                }
        }

        if (more) {
            const int nb = buf ^ 1;
            *(uint4*)&As[nb][lrow * AST + lo16]     = pa0;
            *(uint4*)&As[nb][lrow * AST + lo16 + 8] = pa1;
            *(uint4*)&Bs[nb][bk * BST + bsc]        = f8_to_h8(q0, q1);
            *(uint4*)&Bs[nb][(bk + 16) * BST + bsc] = f8_to_h8(q2, q3);
            __syncthreads();
        }
    }

    // epilogue: silu(gate)*up -> half
    const int g4 = lane >> 2, l4 = lane & 3;
    #pragma unroll
    for (int mt = 0; mt < 2; ++mt)
        #pragma unroll
        for (int rr = 0; rr < 2; ++rr) {
            const int m = m0 + warpM + mt * 16 + g4 + rr * 8;
            if (m >= Mg) continue;
            __half* crow = Cg + (size_t)m * Nh + n0 + warpN;
            #pragma unroll
            for (int nt = 0; nt < 4; ++nt) {
                const float va = silu_mul(accG[mt][nt][rr * 2 + 0], accU[mt][nt][rr * 2 + 0]);
                const float vb = silu_mul(accG[mt][nt][rr * 2 + 1], accU[mt][nt][rr * 2 + 1]);
                *(__half2*)(crow + nt * 8 + 2 * l4) = __floats2half2_rn(va, vb);
            }
        }
}

// ---------------- down GEMM (fp16 mma + ldmatrix, fp32 B direct) ----------------
// CTA 128 rows x 128 out-cols.  B = fp32 [K][HDIM] natural.  A = half [*, K].
// mode 0: out[m] = g_sg[m]*acc.  mode 1: atomicAdd(out[token], w*acc).
__global__ void __launch_bounds__(256, 2)
k_down(const __half* __restrict__ A, const float* __restrict__ B,
       float* __restrict__ out, const int* __restrict__ counts,
       int K, long long astride, long long bstride, int Mfixed, int mode)
{
    const int g  = blockIdx.z;
    const int Mg = counts ? min(counts[g], CAP) : Mfixed;
    const int m0 = blockIdx.y * 128;
    if (m0 >= Mg) return;
    const int n0 = blockIdx.x * 128;

    const __half* Ag = A + (size_t)g * astride;
    const float* Bg  = B + (size_t)g * bstride;

    __shared__ __half As[2][128 * AST];
    __shared__ __half Bs[2][32 * BST];

    const int tid = threadIdx.x;
    const int lrow = tid >> 1;
    const int lo16 = (tid & 1) * 16;
    const __half* ap = nullptr;
    if (m0 + lrow < Mg) ap = Ag + (size_t)(m0 + lrow) * K + lo16;

    const int bc = tid & 15;
    const int bk = tid >> 4;
    const float* bp = Bg + (size_t)bk * HDIM + n0 + bc * 8;
    const int bsc = bc * 8;

    const uint4 z4 = make_uint4(0u, 0u, 0u, 0u);
    {
        uint4 a0 = ap ? *(const uint4*)(ap)     : z4;
        uint4 a1 = ap ? *(const uint4*)(ap + 8) : z4;
        float4 q0 = *(const float4*)(bp);
        float4 q1 = *(const float4*)(bp + 4);
        float4 q2 = *(const float4*)(bp + (size_t)16 * HDIM);
        float4 q3 = *(const float4*)(bp + (size_t)16 * HDIM + 4);
        *(uint4*)&As[0][lrow * AST + lo16]     = a0;
        *(uint4*)&As[0][lrow * AST + lo16 + 8] = a1;
        *(uint4*)&Bs[0][bk * BST + bsc]        = f8_to_h8(q0, q1);
        *(uint4*)&Bs[0][(bk + 16) * BST + bsc] = f8_to_h8(q2, q3);
    }
    __syncthreads();

    const int w = tid >> 5, lane = tid & 31;
    const int warpM = (w >> 1) * 32, warpN = (w & 1) * 64;

    const uint32_t as_u = smem_u32(As);
    const uint32_t bs_u = smem_u32(Bs);
    const uint32_t a_lm = as_u + (uint32_t)(((warpM + (lane & 15)) * AST + ((lane >> 4) * 8)) * 2);
    const uint32_t b_lm = bs_u + (uint32_t)((((lane & 15)) * BST + warpN + ((lane >> 4) * 8)) * 2);

    float acc[2][8][4];
    #pragma unroll
    for (int i = 0; i < 2; i++)
        #pragma unroll
        for (int j = 0; j < 8; j++)
            #pragma unroll
            for (int q = 0; q < 4; q++) acc[i][j][q] = 0.f;

    const int NKB = K / 32;
    for (int kb = 0; kb < NKB; ++kb) {
        const int buf = kb & 1;
        uint4 pa0, pa1;
        float4 q0, q1, q2, q3;
        const bool more = (kb + 1 < NKB);
        if (more) {
            const int ko = (kb + 1) * 32;
            pa0 = ap ? *(const uint4*)(ap + ko)     : z4;
            pa1 = ap ? *(const uint4*)(ap + ko + 8) : z4;
            q0 = *(const float4*)(bp + (size_t)ko * HDIM);
            q1 = *(const float4*)(bp + (size_t)ko * HDIM + 4);
            q2 = *(const float4*)(bp + (size_t)(ko + 16) * HDIM);
            q3 = *(const float4*)(bp + (size_t)(ko + 16) * HDIM + 4);
        }

        const uint32_t abase = a_lm + buf * ABYTES;
        const uint32_t bbase = b_lm + buf * BBYTES;
        #pragma unroll
        for (int ks = 0; ks < 2; ++ks) {
            uint32_t af[2][4];
            ldsm_x4(af[0], abase + ks * 32);
            ldsm_x4(af[1], abase + 16 * AST * 2 + ks * 32);
            uint32_t bf[8][2], t[4];
            const uint32_t brow = bbase + ks * 16 * BST * 2;
            #pragma unroll
            for (int p = 0; p < 4; ++p) {
                ldsm_x4t(t, brow + p * 32);
                bf[2 * p][0] = t[0]; bf[2 * p][1] = t[1];
                bf[2 * p + 1][0] = t[2]; bf[2 * p + 1][1] = t[3];
            }
            #pragma unroll
            for (int mt = 0; mt < 2; ++mt)
                #pragma unroll
                for (int nt = 0; nt < 8; ++nt)
                    mma16(acc[mt][nt], af[mt], bf[nt]);
        }

        if (more) {
            const int nb = buf ^ 1;
            *(uint4*)&As[nb][lrow * AST + lo16]     = pa0;
            *(uint4*)&As[nb][lrow * AST + lo16 + 8] = pa1;
            *(uint4*)&Bs[nb][bk * BST + bsc]        = f8_to_h8(q0, q1);
            *(uint4*)&Bs[nb][(bk + 16) * BST + bsc] = f8_to_h8(q2, q3);
            __syncthreads();
        }
    }

    // epilogue
    const int g4 = lane >> 2, l4 = lane & 3;
    #pragma unroll
    for (int mt = 0; mt < 2; ++mt)
        #pragma unroll
        for (int rr = 0; rr < 2; ++rr) {
            const int m = m0 + warpM + mt * 16 + g4 + rr * 8;
            if (m >= Mg) continue;
            float scale;
            float* orow;
            if (mode == 0) {
                scale = g_sg[m];
                orow = out + (size_t)m * HDIM + n0 + warpN;
            } else {
                const int t = g_etok[g * CAP + m];
                scale = g_slotw[g * CAP + m];
                orow = out + (size_t)t * HDIM + n0 + warpN;
            }
            #pragma unroll
            for (int nt = 0; nt < 8; ++nt) {
                const float va = scale * acc[mt][nt][rr * 2 + 0];
                const float vb = scale * acc[mt][nt][rr * 2 + 1];
                const int c = nt * 8 + 2 * l4;
                if (mode == 0) {
                    float2 v; v.x = va; v.y = vb;
                    *(float2*)(orow + c) = v;
                } else {
                    atomicAdd(orow + c, va);
                    atomicAdd(orow + c + 1, vb);
                }
            }
        }
}

// ---------------- host launch ----------------
extern "C" void kernel_launch(void* const* d_in, const int* in_sizes, int n_in,
                              void* d_out, int out_size)
{
    const float* x    = (const float*)d_in[0]; // [2048][1024]
    const float* wg   = (const float*)d_in[1]; // [1024][64]
    const float* wsg  = (const float*)d_in[2]; // [1024][1]
    const float* wsgu = (const float*)d_in[3]; // [1024][4096]
    const float* wsd  = (const float*)d_in[4]; // [2048][1024]
    const float* wegu = (const float*)d_in[5]; // [64][1024][1024]
    const float* wed  = (const float*)d_in[6]; // [64][512][1024]
    float* out = (float*)d_out;

    __half* xh;   cudaGetSymbolAddress((void**)&xh,   g_xh);
    __half* sact; cudaGetSymbolAddress((void**)&sact, g_sact);
    __half* eact; cudaGetSymbolAddress((void**)&eact, g_eact);
    int*    cnts; cudaGetSymbolAddress((void**)&cnts, g_counts);
    int*    etok; cudaGetSymbolAddress((void**)&etok, g_etok);

    // 1. routing (fp32 exact) + x -> half
    zero_counts_kernel<<<1, 64>>>();
    router_kernel<<<T_TOK, 256>>>(x, wg, wsg);
    f2h_kernel<<<(T_TOK * HDIM / 4 + 255) / 256, 256>>>(x, xh, T_TOK * HDIM);

    // 2. gate_up + SwiGLU (weights read fp32 directly, converted in-kernel)
    k_gateup<<<dim3(ISH / 64, T_TOK / 128, 1), 256>>>(
        xh, nullptr, nullptr, wsgu, sact, ISH, HDIM, 0LL, 0LL, T_TOK);
    k_gateup<<<dim3(IDIM / 64, CAP / 128, NEXP), 256>>>(
        xh, etok, cnts, wegu, eact, IDIM, HDIM,
        (long long)HDIM * 2 * IDIM, (long long)CAP * IDIM, 0);

    // 3. down: shared writes out (sigmoid-gated), experts atomicAdd (router-weighted)
    k_down<<<dim3(HDIM / 128, T_TOK / 128, 1), 256>>>(
        sact, wsd, out, nullptr, ISH, 0LL, 0LL, T_TOK, 0);
    k_down<<<dim3(HDIM / 128, CAP / 128, NEXP), 256>>>(
        eact, wed, out, cnts, IDIM,
        (long long)CAP * IDIM, (long long)IDIM * HDIM, 0, 1);

    (void)in_sizes; (void)n_in; (void)out_size; (void)wsg;
}